// round 3
// baseline (speedup 1.0000x reference)
// Model_star_44006234915144 — lambda * ||F^T F_star||_F^2
// bf16 mma.sync GEMM. CTA tile 128(d) x 256(e), warp tile 64x64 (2x4 warps),
// K-chunk 32, 3-stage smem, 256 thr, grid 8x16 = 128 CTAs (one wave).
#include <cuda_runtime.h>
#include <cuda_bf16.h>
#include <cstdint>

#define DD 2048
#define NN 16384
#define TM 128
#define TN 256
#define KC 32
#define NCH (NN / KC)          // 512
#define STG 3
#define THREADS 256
#define ASZ (KC * TM * 2)      // 8192 B  (A rows: 256B per k)
#define BSZ (KC * TN * 2)      // 16384 B (B rows: 512B per k)
#define STGSZ (ASZ + BSZ)      // 24576
#define SMEMSZ (STG * STGSZ)   // 73728
#define NCTAS ((DD / TN) * (DD / TM))   // 128

__device__ float g_partials[NCTAS];

__device__ __forceinline__ uint32_t smem_u32(const void* p) {
    uint32_t a;
    asm("{ .reg .u64 t; cvta.to.shared.u64 t, %1; cvt.u32.u64 %0, t; }" : "=r"(a) : "l"(p));
    return a;
}
// reg = {hi: bf16(h), lo: bf16(l)}  -> memory order [l, h]
__device__ __forceinline__ uint32_t pack_bf16x2(float h, float l) {
    uint32_t r;
    asm("cvt.rn.bf16x2.f32 %0, %1, %2;" : "=r"(r) : "f"(h), "f"(l));
    return r;
}

#define LDSM_X4_T(r0, r1, r2, r3, ad)                                              \
    asm volatile("ldmatrix.sync.aligned.m8n8.x4.trans.shared.b16 {%0,%1,%2,%3}, [%4];" \
                 : "=r"(r0), "=r"(r1), "=r"(r2), "=r"(r3) : "r"(ad))

#define MMA16816(c, a, b0, b1)                                                     \
    asm volatile("mma.sync.aligned.m16n8k16.row.col.f32.bf16.bf16.f32 "            \
                 "{%0,%1,%2,%3}, {%4,%5,%6,%7}, {%8,%9}, {%0,%1,%2,%3};"           \
                 : "+f"((c)[0]), "+f"((c)[1]), "+f"((c)[2]), "+f"((c)[3])          \
                 : "r"((a)[0]), "r"((a)[1]), "r"((a)[2]), "r"((a)[3]),             \
                   "r"(b0), "r"(b1))

__global__ void __launch_bounds__(THREADS, 1)
gram_kernel(const float* __restrict__ F, const float* __restrict__ Fs) {
    extern __shared__ char smem[];
    const uint32_t sb = smem_u32(smem);
    const int t = threadIdx.x;
    const int L = t & 31;
    const int w = t >> 5;

    const int d0 = blockIdx.y * TM;
    const int e0 = blockIdx.x * TN;

    // ---- global load mapping: thread owns row k_in; A: 16 cols, B: 32 cols ----
    const int k_in = t >> 3;        // 0..31
    const int fq   = t & 7;         // 0..7
    const float4* gA = (const float4*)(F  + (size_t)k_in * DD + d0) + fq * 4;
    const float4* gB = (const float4*)(Fs + (size_t)k_in * DD + e0) + fq * 8;
    const size_t stepf4 = (size_t)KC * DD / 4;

    float4 rA[4], rB[8];

    // ---- mma fragment smem addressing ----
    const int wm = w & 1;           // 2 warps along m (64 each)
    const int wn = w >> 1;          // 4 warps along n (64 each)
    const uint32_t kL     = (uint32_t)((L & 7) + ((L & 16) >> 1));   // 0..15
    const uint32_t rowA   = kL * 256u;
    const uint32_t rowB   = kL * 512u;
    const uint32_t swz    = (uint32_t)(L & 7) << 4;
    const uint32_t aCol   = (uint32_t)((wm * 64 + (L & 8)) * 2);
    const uint32_t bCol   = (uint32_t)((wn * 64 + (L & 8)) * 2);

    float acc[4][8][4];
    #pragma unroll
    for (int i = 0; i < 4; i++)
        #pragma unroll
        for (int j = 0; j < 8; j++)
            #pragma unroll
            for (int q = 0; q < 4; q++) acc[i][j][q] = 0.0f;

    const uint32_t ksw = (uint32_t)(k_in & 7) << 4;

    #define LDGC(c) do {                                                           \
        const float4* pa = gA + (size_t)(c) * stepf4;                              \
        const float4* pb = gB + (size_t)(c) * stepf4;                              \
        _Pragma("unroll")                                                          \
        for (int j = 0; j < 4; j++) rA[j] = pa[j];                                 \
        _Pragma("unroll")                                                          \
        for (int j = 0; j < 8; j++) rB[j] = pb[j];                                 \
    } while (0)

    #define STSC(c) do {                                                           \
        uint32_t stg = sb + (uint32_t)((c) % STG) * STGSZ;                         \
        uint32_t ba = stg + (uint32_t)k_in * 256u;                                 \
        uint32_t bb = stg + ASZ + (uint32_t)k_in * 512u;                           \
        _Pragma("unroll")                                                          \
        for (int j = 0; j < 4; j++) {                                              \
            uint32_t off = ((uint32_t)(fq * 4 + j) * 8u) ^ ksw;                    \
            uint32_t lo = pack_bf16x2(rA[j].y, rA[j].x);                           \
            uint32_t hi = pack_bf16x2(rA[j].w, rA[j].z);                           \
            asm volatile("st.shared.v2.b32 [%0], {%1,%2};"                         \
                         :: "r"(ba + off), "r"(lo), "r"(hi) : "memory");           \
        }                                                                          \
        _Pragma("unroll")                                                          \
        for (int j = 0; j < 8; j++) {                                              \
            uint32_t off = ((uint32_t)(fq * 8 + j) * 8u) ^ ksw;                    \
            uint32_t lo = pack_bf16x2(rB[j].y, rB[j].x);                           \
            uint32_t hi = pack_bf16x2(rB[j].w, rB[j].z);                           \
            asm volatile("st.shared.v2.b32 [%0], {%1,%2};"                         \
                         :: "r"(bb + off), "r"(lo), "r"(hi) : "memory");           \
        }                                                                          \
    } while (0)

    LDGC(0);
    STSC(0);
    LDGC(1);

    #pragma unroll 1
    for (int it = 0; it < NCH; ++it) {
        __syncthreads();
        if (it + 1 < NCH) STSC(it + 1);
        if (it + 2 < NCH) LDGC(it + 2);

        const uint32_t sA = sb + (uint32_t)(it % STG) * STGSZ;
        const uint32_t sB = sA + ASZ;

        #pragma unroll
        for (int kh = 0; kh < 2; kh++) {
            uint32_t a[4][4];
            #pragma unroll
            for (int mt = 0; mt < 4; mt++) {
                uint32_t ad = sA + (uint32_t)kh * 4096u + rowA
                            + ((aCol + (uint32_t)mt * 32u) ^ swz);
                LDSM_X4_T(a[mt][0], a[mt][1], a[mt][2], a[mt][3], ad);
            }
            #pragma unroll
            for (int nt = 0; nt < 4; nt++) {
                uint32_t b0, b1, b2, b3;
                uint32_t bd = sB + (uint32_t)kh * 8192u + rowB
                            + ((bCol + (uint32_t)nt * 32u) ^ swz);
                LDSM_X4_T(b0, b1, b2, b3, bd);
                #pragma unroll
                for (int mt = 0; mt < 4; mt++) {
                    MMA16816(acc[mt][nt * 2 + 0], a[mt], b0, b2);
                    MMA16816(acc[mt][nt * 2 + 1], a[mt], b1, b3);
                }
            }
        }
    }

    // ---------------- square-sum epilogue (deterministic) ----------------
    float s = 0.0f;
    #pragma unroll
    for (int i = 0; i < 4; i++)
        #pragma unroll
        for (int j = 0; j < 8; j++)
            #pragma unroll
            for (int q = 0; q < 4; q++) {
                float v = acc[i][j][q];
                s += v * v;
            }
    #pragma unroll
    for (int o = 16; o > 0; o >>= 1) s += __shfl_xor_sync(0xFFFFFFFFu, s, o);

    __syncthreads();                       // stage buffers dead; reuse for reduction
    float* red = (float*)smem;
    if (L == 0) red[w] = s;
    __syncthreads();
    if (t == 0) {
        float tot = 0.0f;
        #pragma unroll
        for (int i = 0; i < 8; i++) tot += red[i];
        g_partials[blockIdx.y * (DD / TN) + blockIdx.x] = tot;
    }
}

// ---------------- deterministic final reduction ----------------
__global__ void reduce_kernel(const float* __restrict__ lam, float* __restrict__ out) {
    const int t = threadIdx.x;             // 128 threads == NCTAS
    float v = g_partials[t];
    #pragma unroll
    for (int o = 16; o > 0; o >>= 1) v += __shfl_xor_sync(0xFFFFFFFFu, v, o);
    __shared__ float sh[4];
    if ((t & 31) == 0) sh[t >> 5] = v;
    __syncthreads();
    if (t == 0) out[0] = lam[0] * (sh[0] + sh[1] + sh[2] + sh[3]);
}

extern "C" void kernel_launch(void* const* d_in, const int* in_sizes, int n_in,
                              void* d_out, int out_size) {
    const float* F   = (const float*)d_in[0];
    const float* Fst = (const float*)d_in[1];
    const float* lam = (const float*)d_in[2];
    (void)in_sizes; (void)n_in; (void)out_size;

    cudaFuncSetAttribute(gram_kernel, cudaFuncAttributeMaxDynamicSharedMemorySize, SMEMSZ);

    dim3 grid(DD / TN, DD / TM);   // (8, 16) = 128 CTAs
    gram_kernel<<<grid, THREADS, SMEMSZ>>>(F, Fst);
    reduce_kernel<<<1, NCTAS>>>(lam, (float*)d_out);
}

// round 4
// speedup vs baseline: 1.1151x; 1.1151x over previous
// Model_star_44006234915144 — lambda * ||F^T F_star||_F^2
// bf16 mma.sync GEMM. CTA tile 128(d) x 256(e), 512 thr, warp tile 32x64,
// K-chunk 32, 3-stage smem, grid 8x16 = 128 CTAs (one wave, 4 warps/SMSP).
#include <cuda_runtime.h>
#include <cuda_bf16.h>
#include <cstdint>

#define DD 2048
#define NN 16384
#define TM 128
#define TN 256
#define KC 32
#define NCH (NN / KC)          // 512
#define STG 3
#define THREADS 512
#define ASZ (KC * TM * 2)      // 8192 B  (A rows: 256B per k)
#define BSZ (KC * TN * 2)      // 16384 B (B rows: 512B per k)
#define STGSZ (ASZ + BSZ)      // 24576
#define SMEMSZ (STG * STGSZ)   // 73728
#define NCTAS ((DD / TN) * (DD / TM))   // 128

__device__ float g_partials[NCTAS];

__device__ __forceinline__ uint32_t smem_u32(const void* p) {
    uint32_t a;
    asm("{ .reg .u64 t; cvta.to.shared.u64 t, %1; cvt.u32.u64 %0, t; }" : "=r"(a) : "l"(p));
    return a;
}
// reg = {hi: bf16(h), lo: bf16(l)}  -> memory order [l, h]
__device__ __forceinline__ uint32_t pack_bf16x2(float h, float l) {
    uint32_t r;
    asm("cvt.rn.bf16x2.f32 %0, %1, %2;" : "=r"(r) : "f"(h), "f"(l));
    return r;
}

#define LDSM_X4_T(r0, r1, r2, r3, ad)                                              \
    asm volatile("ldmatrix.sync.aligned.m8n8.x4.trans.shared.b16 {%0,%1,%2,%3}, [%4];" \
                 : "=r"(r0), "=r"(r1), "=r"(r2), "=r"(r3) : "r"(ad))

#define MMA16816(c, a, b0, b1)                                                     \
    asm volatile("mma.sync.aligned.m16n8k16.row.col.f32.bf16.bf16.f32 "            \
                 "{%0,%1,%2,%3}, {%4,%5,%6,%7}, {%8,%9}, {%0,%1,%2,%3};"           \
                 : "+f"((c)[0]), "+f"((c)[1]), "+f"((c)[2]), "+f"((c)[3])          \
                 : "r"((a)[0]), "r"((a)[1]), "r"((a)[2]), "r"((a)[3]),             \
                   "r"(b0), "r"(b1))

__global__ void nop_kernel() {}

__global__ void __launch_bounds__(THREADS, 1)
gram_kernel(const float* __restrict__ F, const float* __restrict__ Fs) {
    extern __shared__ char smem[];
    const uint32_t sb = smem_u32(smem);
    const int t = threadIdx.x;
    const int L = t & 31;
    const int w = t >> 5;

    const int d0 = blockIdx.y * TM;
    const int e0 = blockIdx.x * TN;

    // ---- global load mapping: thread owns row k_in; A: 8 cols, B: 16 cols ----
    const int k_in = t >> 4;        // 0..31
    const int fq   = t & 15;        // 0..15
    const float4* gA = (const float4*)(F  + (size_t)k_in * DD + d0) + fq * 2;
    const float4* gB = (const float4*)(Fs + (size_t)k_in * DD + e0) + fq * 4;
    const size_t stepf4 = (size_t)KC * DD / 4;

    float4 rA[2], rB[4];

    // ---- mma fragment smem addressing ----
    const int wm = w & 3;           // 4 warps along m (32 rows each)
    const int wn = w >> 2;          // 4 warps along n (64 cols each)
    const uint32_t kL     = (uint32_t)((L & 7) + ((L & 16) >> 1));   // 0..15
    const uint32_t rowA   = kL * 256u;
    const uint32_t rowB   = kL * 512u;
    const uint32_t swz    = (uint32_t)(L & 7) << 4;
    const uint32_t aCol   = (uint32_t)((wm * 32 + (L & 8)) * 2);
    const uint32_t bCol   = (uint32_t)((wn * 64 + (L & 8)) * 2);

    float acc[2][8][4];
    #pragma unroll
    for (int i = 0; i < 2; i++)
        #pragma unroll
        for (int j = 0; j < 8; j++)
            #pragma unroll
            for (int q = 0; q < 4; q++) acc[i][j][q] = 0.0f;

    const uint32_t ksw = (uint32_t)(k_in & 7) << 4;

    #define LDGC(c) do {                                                           \
        const float4* pa = gA + (size_t)(c) * stepf4;                              \
        const float4* pb = gB + (size_t)(c) * stepf4;                              \
        _Pragma("unroll")                                                          \
        for (int j = 0; j < 2; j++) rA[j] = pa[j];                                 \
        _Pragma("unroll")                                                          \
        for (int j = 0; j < 4; j++) rB[j] = pb[j];                                 \
    } while (0)

    #define STSC(c) do {                                                           \
        uint32_t stg = sb + (uint32_t)((c) % STG) * STGSZ;                         \
        uint32_t ba = stg + (uint32_t)k_in * 256u;                                 \
        uint32_t bb = stg + ASZ + (uint32_t)k_in * 512u;                           \
        _Pragma("unroll")                                                          \
        for (int j = 0; j < 2; j++) {                                              \
            uint32_t off = ((uint32_t)(fq * 2 + j) * 8u) ^ ksw;                    \
            uint32_t lo = pack_bf16x2(rA[j].y, rA[j].x);                           \
            uint32_t hi = pack_bf16x2(rA[j].w, rA[j].z);                           \
            asm volatile("st.shared.v2.b32 [%0], {%1,%2};"                         \
                         :: "r"(ba + off), "r"(lo), "r"(hi) : "memory");           \
        }                                                                          \
        _Pragma("unroll")                                                          \
        for (int j = 0; j < 4; j++) {                                              \
            uint32_t off = ((uint32_t)(fq * 4 + j) * 8u) ^ ksw;                    \
            uint32_t lo = pack_bf16x2(rB[j].y, rB[j].x);                           \
            uint32_t hi = pack_bf16x2(rB[j].w, rB[j].z);                           \
            asm volatile("st.shared.v2.b32 [%0], {%1,%2};"                         \
                         :: "r"(bb + off), "r"(lo), "r"(hi) : "memory");           \
        }                                                                          \
    } while (0)

    LDGC(0);
    STSC(0);
    LDGC(1);

    #pragma unroll 1
    for (int it = 0; it < NCH; ++it) {
        __syncthreads();
        if (it + 1 < NCH) STSC(it + 1);
        if (it + 2 < NCH) LDGC(it + 2);

        const uint32_t sA = sb + (uint32_t)(it % STG) * STGSZ;
        const uint32_t sB = sA + ASZ;

        #pragma unroll
        for (int kh = 0; kh < 2; kh++) {
            uint32_t a[2][4];
            #pragma unroll
            for (int mt = 0; mt < 2; mt++) {
                uint32_t ad = sA + (uint32_t)kh * 4096u + rowA
                            + ((aCol + (uint32_t)mt * 32u) ^ swz);
                LDSM_X4_T(a[mt][0], a[mt][1], a[mt][2], a[mt][3], ad);
            }
            #pragma unroll
            for (int nt = 0; nt < 4; nt++) {
                uint32_t b0, b1, b2, b3;
                uint32_t bd = sB + (uint32_t)kh * 8192u + rowB
                            + ((bCol + (uint32_t)nt * 32u) ^ swz);
                LDSM_X4_T(b0, b1, b2, b3, bd);
                #pragma unroll
                for (int mt = 0; mt < 2; mt++) {
                    MMA16816(acc[mt][nt * 2 + 0], a[mt], b0, b2);
                    MMA16816(acc[mt][nt * 2 + 1], a[mt], b1, b3);
                }
            }
        }
    }

    // ---------------- square-sum epilogue (deterministic) ----------------
    float s = 0.0f;
    #pragma unroll
    for (int i = 0; i < 2; i++)
        #pragma unroll
        for (int j = 0; j < 8; j++)
            #pragma unroll
            for (int q = 0; q < 4; q++) {
                float v = acc[i][j][q];
                s += v * v;
            }
    #pragma unroll
    for (int o = 16; o > 0; o >>= 1) s += __shfl_xor_sync(0xFFFFFFFFu, s, o);

    __syncthreads();                       // stage buffers dead; reuse for reduction
    float* red = (float*)smem;
    if (L == 0) red[w] = s;
    __syncthreads();
    if (t == 0) {
        float tot = 0.0f;
        #pragma unroll
        for (int i = 0; i < 16; i++) tot += red[i];
        g_partials[blockIdx.y * (DD / TN) + blockIdx.x] = tot;
    }
}

// ---------------- deterministic final reduction ----------------
__global__ void reduce_kernel(const float* __restrict__ lam, float* __restrict__ out) {
    const int t = threadIdx.x;             // 128 threads == NCTAS
    float v = g_partials[t];
    #pragma unroll
    for (int o = 16; o > 0; o >>= 1) v += __shfl_xor_sync(0xFFFFFFFFu, v, o);
    __shared__ float sh[4];
    if ((t & 31) == 0) sh[t >> 5] = v;
    __syncthreads();
    if (t == 0) out[0] = lam[0] * (sh[0] + sh[1] + sh[2] + sh[3]);
}

extern "C" void kernel_launch(void* const* d_in, const int* in_sizes, int n_in,
                              void* d_out, int out_size) {
    const float* F   = (const float*)d_in[0];
    const float* Fst = (const float*)d_in[1];
    const float* lam = (const float*)d_in[2];
    (void)in_sizes; (void)n_in; (void)out_size;

    cudaFuncSetAttribute(gram_kernel, cudaFuncAttributeMaxDynamicSharedMemorySize, SMEMSZ);

    // 4 launches/call so ncu's "-s 5 -c 1" lands on gram_kernel
    // (launch idx 5 = 2nd call's position 1), not reduce_kernel.
    nop_kernel<<<1, 32>>>();
    dim3 grid(DD / TN, DD / TM);   // (8, 16) = 128 CTAs
    gram_kernel<<<grid, THREADS, SMEMSZ>>>(F, Fst);
    reduce_kernel<<<1, NCTAS>>>(lam, (float*)d_out);
    nop_kernel<<<1, 32>>>();
}